// round 1
// baseline (speedup 1.0000x reference)
#include <cuda_runtime.h>

// ---------------------------------------------------------------------------
// Problem constants
// ---------------------------------------------------------------------------
namespace {
constexpr int NB   = 2048;          // batch (tokens)
constexpr int SPOT = 1024;
constexpr int IMG  = 1024;
constexpr int PROJ = 256;
constexpr int NH   = 8;
constexpr int DH   = 64;
constexpr int INNER = NH * DH;      // 512
constexpr int MLPD = 2048;
constexpr int QKVW = 3 * INNER;     // 1536
constexpr int NL   = 2;
}

// ---------------------------------------------------------------------------
// Scratch (static device allocations; allowed per harness rules)
// ---------------------------------------------------------------------------
__device__ float g_spot  [NB * SPOT];
__device__ float g_hbuf  [NB * SPOT];
__device__ float g_qkv   [NB * QKVW];
__device__ float g_attno [NB * INNER];
__device__ float g_mlp   [NB * MLPD];
__device__ float g_pimg  [NB * PROJ];
__device__ float g_eimg  [NB * PROJ];
__device__ float g_pspot [NB * PROJ];
__device__ float g_espot [NB * PROJ];
__device__ float g_cat   [NB * 2 * PROJ];
__device__ float g_logits[NB * NB];
__device__ float g_tgt   [NB * NB];
__device__ float g_rowp  [NB];
__device__ float g_colp  [NB];

// ---------------------------------------------------------------------------
// Device helpers
// ---------------------------------------------------------------------------
__device__ __forceinline__ float gelu_f(float x) {
    return 0.5f * x * (1.0f + erff(x * 0.7071067811865475f));
}

__device__ __forceinline__ float blk_sum256(float v, float* sh) {
    int t = threadIdx.x;
    sh[t] = v; __syncthreads();
    #pragma unroll
    for (int s = 128; s >= 1; s >>= 1) {
        if (t < s) sh[t] += sh[t + s];
        __syncthreads();
    }
    float r = sh[0]; __syncthreads();
    return r;
}

__device__ __forceinline__ float blk_max256(float v, float* sh) {
    int t = threadIdx.x;
    sh[t] = v; __syncthreads();
    #pragma unroll
    for (int s = 128; s >= 1; s >>= 1) {
        if (t < s) sh[t] = fmaxf(sh[t], sh[t + s]);
        __syncthreads();
    }
    float r = sh[0]; __syncthreads();
    return r;
}

// ---------------------------------------------------------------------------
// Embedding: spot = expression + x_table[x_idx] + y_table[y_idx]
// ---------------------------------------------------------------------------
__global__ __launch_bounds__(256) void embed_kernel(
    const float* __restrict__ expr, const float* __restrict__ xt,
    const float* __restrict__ yt, const int* __restrict__ xi,
    const int* __restrict__ yi, float* __restrict__ out)
{
    int row = blockIdx.x;
    size_t xo = (size_t)xi[row] * SPOT;
    size_t yo = (size_t)yi[row] * SPOT;
    size_t ro = (size_t)row * SPOT;
    for (int j = threadIdx.x; j < SPOT; j += 256)
        out[ro + j] = expr[ro + j] + xt[xo + j] + yt[yo + j];
}

// ---------------------------------------------------------------------------
// LayerNorm (row-wise, exact two-pass). CNT = N/256 (1 or 4).
// In-place safe (values cached in registers before output write).
// ---------------------------------------------------------------------------
template<int CNT>
__global__ __launch_bounds__(256) void ln_kernel(
    const float* __restrict__ x, const float* __restrict__ g,
    const float* __restrict__ b, float* __restrict__ out)
{
    __shared__ float sh[256];
    const int N = CNT * 256;
    int row = blockIdx.x, tid = threadIdx.x;
    const float* xr = x + (size_t)row * N;
    float vals[CNT];
    float s = 0.f;
    #pragma unroll
    for (int i = 0; i < CNT; i++) { vals[i] = xr[i * 256 + tid]; s += vals[i]; }
    s = blk_sum256(s, sh);
    float mean = s / N;
    float ss = 0.f;
    #pragma unroll
    for (int i = 0; i < CNT; i++) { float d = vals[i] - mean; ss += d * d; }
    ss = blk_sum256(ss, sh);
    float rstd = rsqrtf(ss / N + 1e-5f);
    float* orow = out + (size_t)row * N;
    #pragma unroll
    for (int i = 0; i < CNT; i++) {
        int j = i * 256 + tid;
        orow[j] = (vals[i] - mean) * rstd * g[j] + b[j];
    }
}

// ---------------------------------------------------------------------------
// Generic fp32 GEMM: C = epi( scale*(A @ op(B)) + bias ) + res
//   A: [M,K] row-major (optionally GELU applied to A on load)
//   B: [K,N] row-major, or [N,K] row-major if TRANSB
// 128x128 tile, BK=16, 256 threads, 8x8 per thread.
// Requires M%128==0, N%128==0, K%16==0.
// ---------------------------------------------------------------------------
template<bool TRANSB, bool GELU_EPI, bool GELU_A>
__global__ __launch_bounds__(256) void gemm128(
    const float* __restrict__ A, const float* __restrict__ Bm,
    const float* __restrict__ bias, const float* __restrict__ res,
    float* __restrict__ C, int M, int N, int K, float scale)
{
    __shared__ float As[16][132];
    __shared__ float Bs[16][132];
    const int tid = threadIdx.x;
    const int bm = blockIdx.y * 128;
    const int bn = blockIdx.x * 128;
    const int tm = (tid >> 4) * 8;
    const int tn = (tid & 15) * 8;

    float acc[8][8];
    #pragma unroll
    for (int i = 0; i < 8; i++)
        #pragma unroll
        for (int j = 0; j < 8; j++) acc[i][j] = 0.f;

    for (int kt = 0; kt < K; kt += 16) {
        // ---- load A tile (128 rows x 16 k), store transposed As[k][m]
        #pragma unroll
        for (int it = 0; it < 2; it++) {
            int s = tid + it * 256;          // 0..511
            int row = s >> 2;                // 0..127
            int kq = (s & 3) * 4;            // 0,4,8,12
            float4 v = *reinterpret_cast<const float4*>(
                &A[(size_t)(bm + row) * K + kt + kq]);
            if (GELU_A) {
                v.x = gelu_f(v.x); v.y = gelu_f(v.y);
                v.z = gelu_f(v.z); v.w = gelu_f(v.w);
            }
            As[kq + 0][row] = v.x; As[kq + 1][row] = v.y;
            As[kq + 2][row] = v.z; As[kq + 3][row] = v.w;
        }
        // ---- load B tile -> Bs[k][n]
        if (!TRANSB) {
            #pragma unroll
            for (int it = 0; it < 2; it++) {
                int s = tid + it * 256;
                int kb = s >> 5;             // 0..15
                int nq = (s & 31) * 4;       // 0..124
                float4 v = *reinterpret_cast<const float4*>(
                    &Bm[(size_t)(kt + kb) * N + bn + nq]);
                *reinterpret_cast<float4*>(&Bs[kb][nq]) = v;
            }
        } else {
            #pragma unroll
            for (int it = 0; it < 2; it++) {
                int s = tid + it * 256;
                int row = s >> 2;            // n 0..127
                int kq = (s & 3) * 4;
                float4 v = *reinterpret_cast<const float4*>(
                    &Bm[(size_t)(bn + row) * K + kt + kq]);
                Bs[kq + 0][row] = v.x; Bs[kq + 1][row] = v.y;
                Bs[kq + 2][row] = v.z; Bs[kq + 3][row] = v.w;
            }
        }
        __syncthreads();
        // ---- compute
        #pragma unroll
        for (int kk = 0; kk < 16; kk++) {
            float4 a0 = *reinterpret_cast<const float4*>(&As[kk][tm]);
            float4 a1 = *reinterpret_cast<const float4*>(&As[kk][tm + 4]);
            float4 b0 = *reinterpret_cast<const float4*>(&Bs[kk][tn]);
            float4 b1 = *reinterpret_cast<const float4*>(&Bs[kk][tn + 4]);
            float av[8] = {a0.x, a0.y, a0.z, a0.w, a1.x, a1.y, a1.z, a1.w};
            float bv[8] = {b0.x, b0.y, b0.z, b0.w, b1.x, b1.y, b1.z, b1.w};
            #pragma unroll
            for (int i = 0; i < 8; i++)
                #pragma unroll
                for (int j = 0; j < 8; j++)
                    acc[i][j] += av[i] * bv[j];
        }
        __syncthreads();
    }
    // ---- epilogue
    #pragma unroll
    for (int i = 0; i < 8; i++) {
        int row = bm + tm + i;
        #pragma unroll
        for (int j = 0; j < 8; j++) {
            int col = bn + tn + j;
            float v = acc[i][j] * scale;
            if (bias) v += bias[col];
            if (GELU_EPI) v = gelu_f(v);
            if (res) v += res[(size_t)row * N + col];
            C[(size_t)row * N + col] = v;
        }
    }
}

// ---------------------------------------------------------------------------
// Fused flash attention, fp32.
// grid: (NB/64, NH). 64 queries x 64 keys per tile, DH=64, online softmax.
// qkv layout [NB, 1536] = [q(8x64) | k(8x64) | v(8x64)].
// Output merged heads: o[NB, 512], o[r, h*64+d].
// ---------------------------------------------------------------------------
#define ATTN_SMEM ((4 * 64 * 68 + 3 * 64) * 4)

__global__ __launch_bounds__(256) void attn_kernel(
    const float* __restrict__ qkv, float* __restrict__ o)
{
    extern __shared__ float sm[];
    float* sQt = sm;                 // [d][q]  stride 68
    float* sKt = sm + 64 * 68;       // [d][j]
    float* sV  = sm + 2 * 64 * 68;   // [j][d]
    float* sP  = sm + 3 * 64 * 68;   // [q][j]
    float* rm  = sm + 4 * 64 * 68;   // running max [64]
    float* rl  = rm + 64;            // running sum [64]
    float* ra  = rl + 64;            // alpha       [64]

    const int tid = threadIdx.x;
    const int q0 = blockIdx.x * 64;
    const int h  = blockIdx.y;

    // load Q tile (transposed: sQt[d][q])
    const float* qbase = qkv + (size_t)q0 * QKVW + h * 64;
    for (int idx = tid; idx < 4096; idx += 256) {
        int q = idx >> 6, d = idx & 63;
        sQt[d * 68 + q] = qbase[(size_t)q * QKVW + d];
    }
    if (tid < 64) { rm[tid] = -1e30f; rl[tid] = 0.f; }

    const int rq = (tid >> 4) * 4;   // query sub-row base (0..60)
    const int rc = (tid & 15) * 4;   // key col base / dim base (0..60)
    float acc[4][4];
    #pragma unroll
    for (int i = 0; i < 4; i++)
        #pragma unroll
        for (int j = 0; j < 4; j++) acc[i][j] = 0.f;

    for (int jt = 0; jt < NB / 64; jt++) {
        __syncthreads();   // protect sKt/sV/sP from previous iteration use
        const float* kbase = qkv + (size_t)(jt * 64) * QKVW + INNER + h * 64;
        const float* vbase = kbase + INNER;
        for (int idx = tid; idx < 4096; idx += 256) {
            int j = idx >> 6, d = idx & 63;
            sKt[d * 68 + j] = kbase[(size_t)j * QKVW + d];
            sV [j * 68 + d] = vbase[(size_t)j * QKVW + d];
        }
        __syncthreads();

        // S = Q K^T * 0.125  (each thread: 4x4 micro-tile)
        float sacc[4][4];
        #pragma unroll
        for (int i = 0; i < 4; i++)
            #pragma unroll
            for (int j = 0; j < 4; j++) sacc[i][j] = 0.f;
        #pragma unroll 16
        for (int kk = 0; kk < 64; kk++) {
            float4 qv = *reinterpret_cast<const float4*>(&sQt[kk * 68 + rq]);
            float4 kv = *reinterpret_cast<const float4*>(&sKt[kk * 68 + rc]);
            float qa[4] = {qv.x, qv.y, qv.z, qv.w};
            float ka[4] = {kv.x, kv.y, kv.z, kv.w};
            #pragma unroll
            for (int i = 0; i < 4; i++)
                #pragma unroll
                for (int j = 0; j < 4; j++)
                    sacc[i][j] += qa[i] * ka[j];
        }
        #pragma unroll
        for (int i = 0; i < 4; i++)
            #pragma unroll
            for (int j = 0; j < 4; j++)
                sP[(rq + i) * 68 + rc + j] = sacc[i][j] * 0.125f;
        __syncthreads();

        // online softmax row update (one thread per query row)
        if (tid < 64) {
            float mold = rm[tid];
            float mx = mold;
            float* row = &sP[tid * 68];
            #pragma unroll 8
            for (int j = 0; j < 64; j++) mx = fmaxf(mx, row[j]);
            float a = __expf(mold - mx);
            float s = 0.f;
            #pragma unroll 8
            for (int j = 0; j < 64; j++) {
                float p = __expf(row[j] - mx);
                row[j] = p; s += p;
            }
            rl[tid] = rl[tid] * a + s;
            rm[tid] = mx;
            ra[tid] = a;
        }
        __syncthreads();

        // acc = acc*alpha + P @ V
        float al[4];
        #pragma unroll
        for (int i = 0; i < 4; i++) al[i] = ra[rq + i];
        #pragma unroll
        for (int i = 0; i < 4; i++)
            #pragma unroll
            for (int j = 0; j < 4; j++) acc[i][j] *= al[i];
        #pragma unroll 8
        for (int j = 0; j < 64; j++) {
            float4 vv = *reinterpret_cast<const float4*>(&sV[j * 68 + rc]);
            float va[4] = {vv.x, vv.y, vv.z, vv.w};
            float p[4];
            #pragma unroll
            for (int i = 0; i < 4; i++) p[i] = sP[(rq + i) * 68 + j];
            #pragma unroll
            for (int i = 0; i < 4; i++)
                #pragma unroll
                for (int d = 0; d < 4; d++)
                    acc[i][d] += p[i] * va[d];
        }
    }

    // write normalized output
    #pragma unroll
    for (int i = 0; i < 4; i++) {
        float inv = 1.f / rl[rq + i];
        #pragma unroll
        for (int d = 0; d < 4; d++)
            o[(size_t)(q0 + rq + i) * INNER + h * 64 + rc + d] = acc[i][d] * inv;
    }
}

// ---------------------------------------------------------------------------
// Pack cat = [img_e | spot_e]  (NB x 512)
// ---------------------------------------------------------------------------
__global__ __launch_bounds__(256) void pack_kernel(
    const float* __restrict__ ie, const float* __restrict__ se,
    float* __restrict__ cat)
{
    int row = blockIdx.x;
    for (int j = threadIdx.x; j < 2 * PROJ; j += 256) {
        float v = (j < PROJ) ? ie[(size_t)row * PROJ + j]
                             : se[(size_t)row * PROJ + j - PROJ];
        cat[(size_t)row * 2 * PROJ + j] = v;
    }
}

// ---------------------------------------------------------------------------
// Row softmax in place (N=2048)
// ---------------------------------------------------------------------------
__global__ __launch_bounds__(256) void softmax_rows(float* __restrict__ x)
{
    __shared__ float sh[256];
    int row = blockIdx.x, tid = threadIdx.x;
    float* r = x + (size_t)row * NB;
    float v[8];
    float mx = -1e30f;
    #pragma unroll
    for (int i = 0; i < 8; i++) { v[i] = r[i * 256 + tid]; mx = fmaxf(mx, v[i]); }
    mx = blk_max256(mx, sh);
    float s = 0.f;
    #pragma unroll
    for (int i = 0; i < 8; i++) { v[i] = __expf(v[i] - mx); s += v[i]; }
    s = blk_sum256(s, sh);
    float inv = 1.f / s;
    #pragma unroll
    for (int i = 0; i < 8; i++) r[i * 256 + tid] = v[i] * inv;
}

// ---------------------------------------------------------------------------
// Row loss: rowp[i] = 0.5*(LSE_row(logits,i) - sum_j t[i,j]*l[i,j])
// ---------------------------------------------------------------------------
__global__ __launch_bounds__(256) void rowloss_kernel(
    const float* __restrict__ logits, const float* __restrict__ tgt,
    float* __restrict__ rowp)
{
    __shared__ float sh[256];
    int row = blockIdx.x, tid = threadIdx.x;
    const float* lr = logits + (size_t)row * NB;
    const float* tr = tgt    + (size_t)row * NB;
    float lv[8], tv[8];
    float mx = -1e30f;
    #pragma unroll
    for (int i = 0; i < 8; i++) {
        lv[i] = lr[i * 256 + tid];
        tv[i] = tr[i * 256 + tid];
        mx = fmaxf(mx, lv[i]);
    }
    mx = blk_max256(mx, sh);
    float se = 0.f, dot = 0.f;
    #pragma unroll
    for (int i = 0; i < 8; i++) { se += __expf(lv[i] - mx); dot += tv[i] * lv[i]; }
    se  = blk_sum256(se, sh);
    dot = blk_sum256(dot, sh);
    if (tid == 0) rowp[row] = 0.5f * (mx + logf(se) - dot);
}

// ---------------------------------------------------------------------------
// Column loss: colp[c] = 0.5*( (sum_j t[j,c]) * LSE_col(logits,c)
//                              - sum_j t[j,c]*l[j,c] )
// grid: NB/64 blocks, 256 threads = 4 row-lanes x 64 cols.
// ---------------------------------------------------------------------------
__global__ __launch_bounds__(256) void colloss_kernel(
    const float* __restrict__ logits, const float* __restrict__ tgt,
    float* __restrict__ colp)
{
    __shared__ float smx[256], sse[256], sts[256], stdot[256];
    int tid = threadIdx.x;
    int c = blockIdx.x * 64 + (tid & 63);
    int ry = tid >> 6;
    float mx = -1e30f, se = 0.f, ts = 0.f, td = 0.f;
    for (int r = ry; r < NB; r += 4) {
        float l = logits[(size_t)r * NB + c];
        float t = tgt   [(size_t)r * NB + c];
        if (l > mx) { se = se * __expf(mx - l) + 1.f; mx = l; }
        else        { se += __expf(l - mx); }
        ts += t;
        td += t * l;
    }
    smx[tid] = mx; sse[tid] = se; sts[tid] = ts; stdot[tid] = td;
    __syncthreads();
    if (ry == 0) {
        #pragma unroll
        for (int k = 1; k < 4; k++) {
            int o = tid + k * 64;
            float m2 = smx[o], s2 = sse[o];
            float m = fmaxf(mx, m2);
            se = se * __expf(mx - m) + s2 * __expf(m2 - m);
            mx = m;
            ts += sts[o];
            td += stdot[o];
        }
        colp[c] = 0.5f * (ts * (mx + logf(se)) - td);
    }
}

// ---------------------------------------------------------------------------
// Final deterministic reduction -> scalar loss
// ---------------------------------------------------------------------------
__global__ __launch_bounds__(256) void final_reduce(
    const float* __restrict__ a, const float* __restrict__ b,
    float* __restrict__ out)
{
    __shared__ float sh[256];
    int tid = threadIdx.x;
    float s = 0.f;
    for (int i = tid; i < NB; i += 256) s += a[i] + b[i];
    s = blk_sum256(s, sh);
    if (tid == 0) out[0] = s * (1.0f / NB);
}

// ---------------------------------------------------------------------------
// Host launch
// ---------------------------------------------------------------------------
extern "C" void kernel_launch(void* const* d_in, const int* in_sizes, int n_in,
                              void* d_out, int out_size)
{
    (void)in_sizes; (void)n_in; (void)out_size;
    const float* image_features = (const float*)d_in[0];
    const float* expression     = (const float*)d_in[1];
    const float* x_table        = (const float*)d_in[2];
    const float* y_table        = (const float*)d_in[3];
    const float* ln1_g          = (const float*)d_in[4];
    const float* ln1_b          = (const float*)d_in[5];
    const float* w_qkv          = (const float*)d_in[6];
    const float* w_o            = (const float*)d_in[7];
    const float* b_o            = (const float*)d_in[8];
    const float* ln2_g          = (const float*)d_in[9];
    const float* ln2_b          = (const float*)d_in[10];
    const float* w1             = (const float*)d_in[11];
    const float* b1             = (const float*)d_in[12];
    const float* w2             = (const float*)d_in[13];
    const float* b2             = (const float*)d_in[14];
    const float* img_proj_w     = (const float*)d_in[15];
    const float* img_proj_b     = (const float*)d_in[16];
    const float* img_fc_w       = (const float*)d_in[17];
    const float* img_fc_b       = (const float*)d_in[18];
    const float* img_ln_g       = (const float*)d_in[19];
    const float* img_ln_b       = (const float*)d_in[20];
    const float* spot_proj_w    = (const float*)d_in[21];
    const float* spot_proj_b    = (const float*)d_in[22];
    const float* spot_fc_w      = (const float*)d_in[23];
    const float* spot_fc_b      = (const float*)d_in[24];
    const float* spot_ln_g      = (const float*)d_in[25];
    const float* spot_ln_b      = (const float*)d_in[26];
    const int*   x_idx          = (const int*)d_in[27];
    const int*   y_idx          = (const int*)d_in[28];
    float* out = (float*)d_out;

    float *spot, *hbuf, *qkvb, *attno, *mlpb, *pimg, *eimg, *pspot, *espot;
    float *cat, *logits, *tgt, *rowp, *colp;
    cudaGetSymbolAddress((void**)&spot,  g_spot);
    cudaGetSymbolAddress((void**)&hbuf,  g_hbuf);
    cudaGetSymbolAddress((void**)&qkvb,  g_qkv);
    cudaGetSymbolAddress((void**)&attno, g_attno);
    cudaGetSymbolAddress((void**)&mlpb,  g_mlp);
    cudaGetSymbolAddress((void**)&pimg,  g_pimg);
    cudaGetSymbolAddress((void**)&eimg,  g_eimg);
    cudaGetSymbolAddress((void**)&pspot, g_pspot);
    cudaGetSymbolAddress((void**)&espot, g_espot);
    cudaGetSymbolAddress((void**)&cat,   g_cat);
    cudaGetSymbolAddress((void**)&logits,g_logits);
    cudaGetSymbolAddress((void**)&tgt,   g_tgt);
    cudaGetSymbolAddress((void**)&rowp,  g_rowp);
    cudaGetSymbolAddress((void**)&colp,  g_colp);

    cudaFuncSetAttribute(attn_kernel,
                         cudaFuncAttributeMaxDynamicSharedMemorySize, ATTN_SMEM);

    // 1. embedding
    embed_kernel<<<NB, 256>>>(expression, x_table, y_table, x_idx, y_idx, spot);

    // 2. transformer layers
    for (int l = 0; l < NL; l++) {
        const float* wqkv_l = w_qkv + (size_t)l * SPOT * QKVW;
        const float* wo_l   = w_o   + (size_t)l * INNER * SPOT;
        const float* bo_l   = b_o   + (size_t)l * SPOT;
        const float* w1_l   = w1    + (size_t)l * SPOT * MLPD;
        const float* b1_l   = b1    + (size_t)l * MLPD;
        const float* w2_l   = w2    + (size_t)l * MLPD * SPOT;
        const float* b2_l   = b2    + (size_t)l * SPOT;

        ln_kernel<4><<<NB, 256>>>(spot, ln1_g + l * SPOT, ln1_b + l * SPOT, hbuf);
        gemm128<false, false, false><<<dim3(QKVW / 128, NB / 128), 256>>>(
            hbuf, wqkv_l, nullptr, nullptr, qkvb, NB, QKVW, SPOT, 1.f);
        attn_kernel<<<dim3(NB / 64, NH), 256, ATTN_SMEM>>>(qkvb, attno);
        gemm128<false, false, false><<<dim3(SPOT / 128, NB / 128), 256>>>(
            attno, wo_l, bo_l, spot, spot, NB, SPOT, INNER, 1.f);
        ln_kernel<4><<<NB, 256>>>(spot, ln2_g + l * SPOT, ln2_b + l * SPOT, hbuf);
        gemm128<false, true, false><<<dim3(MLPD / 128, NB / 128), 256>>>(
            hbuf, w1_l, b1_l, nullptr, mlpb, NB, MLPD, SPOT, 1.f);
        gemm128<false, false, false><<<dim3(SPOT / 128, NB / 128), 256>>>(
            mlpb, w2_l, b2_l, spot, spot, NB, SPOT, MLPD, 1.f);
    }

    // 3. projection heads
    // img: p = x@wp + bp ; e_pre = gelu(p)@wf + bf + p ; e = LN(e_pre)
    gemm128<false, false, false><<<dim3(PROJ / 128, NB / 128), 256>>>(
        image_features, img_proj_w, img_proj_b, nullptr, pimg, NB, PROJ, IMG, 1.f);
    gemm128<false, false, true><<<dim3(PROJ / 128, NB / 128), 256>>>(
        pimg, img_fc_w, img_fc_b, pimg, eimg, NB, PROJ, PROJ, 1.f);
    ln_kernel<1><<<NB, 256>>>(eimg, img_ln_g, img_ln_b, eimg);

    gemm128<false, false, false><<<dim3(PROJ / 128, NB / 128), 256>>>(
        spot, spot_proj_w, spot_proj_b, nullptr, pspot, NB, PROJ, SPOT, 1.f);
    gemm128<false, false, true><<<dim3(PROJ / 128, NB / 128), 256>>>(
        pspot, spot_fc_w, spot_fc_b, pspot, espot, NB, PROJ, PROJ, 1.f);
    ln_kernel<1><<<NB, 256>>>(espot, spot_ln_g, spot_ln_b, espot);

    // 4. loss
    pack_kernel<<<NB, 256>>>(eimg, espot, cat);
    // logits = spot_e @ img_e^T
    gemm128<true, false, false><<<dim3(NB / 128, NB / 128), 256>>>(
        espot, eimg, nullptr, nullptr, logits, NB, NB, PROJ, 1.f);
    // targets_pre = 0.5 * cat @ cat^T
    gemm128<true, false, false><<<dim3(NB / 128, NB / 128), 256>>>(
        cat, cat, nullptr, nullptr, tgt, NB, NB, 2 * PROJ, 0.5f);
    softmax_rows<<<NB, 256>>>(tgt);
    rowloss_kernel<<<NB, 256>>>(logits, tgt, rowp);
    colloss_kernel<<<NB / 64, 256>>>(logits, tgt, colp);
    final_reduce<<<1, 256>>>(rowp, colp, out);
}

// round 3
// speedup vs baseline: 2.2698x; 2.2698x over previous
#include <cuda_runtime.h>
#include <cstdint>

// ---------------------------------------------------------------------------
// Problem constants
// ---------------------------------------------------------------------------
namespace {
constexpr int NB   = 2048;
constexpr int SPOT = 1024;
constexpr int IMG  = 1024;
constexpr int PROJ = 256;
constexpr int NH   = 8;
constexpr int DH   = 64;
constexpr int INNER = NH * DH;      // 512
constexpr int MLPD = 2048;
constexpr int QKVW = 3 * INNER;     // 1536
constexpr int NL   = 2;
}

// ---------------------------------------------------------------------------
// Scratch
// ---------------------------------------------------------------------------
__device__ float g_spot  [NB * SPOT];
__device__ float g_hbuf  [NB * SPOT];
__device__ float g_qkv   [NB * QKVW];
__device__ float g_attno [NB * INNER];
__device__ float g_mlp   [NB * MLPD];
__device__ float g_S     [(size_t)NH * NB * NB];   // attention scores
__device__ float g_pimg  [NB * PROJ];
__device__ float g_eimg  [NB * PROJ];
__device__ float g_pspot [NB * PROJ];
__device__ float g_espot [NB * PROJ];
__device__ float g_cat   [NB * 2 * PROJ];
__device__ float g_logits[NB * NB];
__device__ float g_tgt   [NB * NB];
__device__ float g_rowp  [NB];
__device__ float g_colp  [NB];

// ---------------------------------------------------------------------------
// Helpers
// ---------------------------------------------------------------------------
__device__ __forceinline__ uint32_t smem_u32(const void* p) {
    uint32_t a;
    asm("{ .reg .u64 t; cvta.to.shared.u64 t, %1; cvt.u32.u64 %0, t; }"
        : "=r"(a) : "l"(p));
    return a;
}

__device__ __forceinline__ float gelu_f(float x) {
    return 0.5f * x * (1.0f + erff(x * 0.7071067811865475f));
}

// split fp32 pair -> packed bf16x2 hi and lo  (memory order: f0 = low half)
__device__ __forceinline__ void split2(float f0, float f1, uint32_t& hi, uint32_t& lo) {
    asm("cvt.rn.bf16x2.f32 %0, %1, %2;" : "=r"(hi) : "f"(f1), "f"(f0));
    float h0 = __uint_as_float(hi << 16);
    float h1 = __uint_as_float(hi & 0xFFFF0000u);
    float l0 = f0 - h0, l1 = f1 - h1;
    asm("cvt.rn.bf16x2.f32 %0, %1, %2;" : "=r"(lo) : "f"(l1), "f"(l0));
}

__device__ __forceinline__ void splitstore4(float4 v, char* hb, char* lb,
                                            int byteoff, bool dogelu) {
    if (dogelu) {
        v.x = gelu_f(v.x); v.y = gelu_f(v.y);
        v.z = gelu_f(v.z); v.w = gelu_f(v.w);
    }
    uint32_t h0, l0, h1, l1;
    split2(v.x, v.y, h0, l0);
    split2(v.z, v.w, h1, l1);
    *reinterpret_cast<uint2*>(hb + byteoff) = make_uint2(h0, h1);
    *reinterpret_cast<uint2*>(lb + byteoff) = make_uint2(l0, l1);
}

#define LDSM_X4(r, a)                                                          \
    asm volatile("ldmatrix.sync.aligned.m8n8.x4.shared.b16 {%0,%1,%2,%3}, [%4];" \
        : "=r"((r)[0]), "=r"((r)[1]), "=r"((r)[2]), "=r"((r)[3]) : "r"(a))
#define LDSM_X2(r, a)                                                          \
    asm volatile("ldmatrix.sync.aligned.m8n8.x2.shared.b16 {%0,%1}, [%2];"     \
        : "=r"((r)[0]), "=r"((r)[1]) : "r"(a))
#define LDSM_X2T(r, a)                                                         \
    asm volatile("ldmatrix.sync.aligned.m8n8.x2.trans.shared.b16 {%0,%1}, [%2];" \
        : "=r"((r)[0]), "=r"((r)[1]) : "r"(a))
#define MMA16816(d, a, b)                                                      \
    asm volatile("mma.sync.aligned.m16n8k16.row.col.f32.bf16.bf16.f32 "        \
        "{%0,%1,%2,%3}, {%4,%5,%6,%7}, {%8,%9}, {%0,%1,%2,%3};"                \
        : "+f"((d)[0]), "+f"((d)[1]), "+f"((d)[2]), "+f"((d)[3])               \
        : "r"((a)[0]), "r"((a)[1]), "r"((a)[2]), "r"((a)[3]),                  \
          "r"((b)[0]), "r"((b)[1]))

// ---------------------------------------------------------------------------
// Split-bf16 tensor-core GEMM (mma.sync path, works on plain sm_103 target).
//   D[M,N] = epi( scale * A @ op(B) + bias ) + res
//   A: [M,K] row-major (optionally GELU on load)
//   B: BNAT ? [N,K] row-major : [K,N] row-major
//   Block tile 128 x NT (NT in {64,128}), BK=32, 256 threads.
//   grid (N/NT, M/128, Z) with element z-strides az/bz/cz.
//   EPI: 0 none, 1 +bias, 2 +bias+gelu, 3 +bias+res
// ---------------------------------------------------------------------------
template<int NT, bool BNAT, bool GELUA, int EPI>
__global__ __launch_bounds__(256) void gemm_mma(
    const float* __restrict__ A, int lda, long long az,
    const float* __restrict__ B, int ldb, long long bz,
    const float* __restrict__ bias, const float* __restrict__ res,
    float* __restrict__ C, int ldc, long long cz,
    int K, float scale)
{
    constexpr int WARPS_N = NT / 32;
    constexpr int WARPS_M = 8 / WARPS_N;
    constexpr int WM = 128 / WARPS_M;           // warp m extent
    constexpr int MT = WM / 16;                 // m16 tiles per warp
    constexpr int ASZ = 128 * 40 * 2;           // bf16 bytes, stride 40
    constexpr int BSZ = BNAT ? NT * 40 * 2 : 32 * (NT + 8) * 2;
    constexpr int STAGE = 2 * ASZ + 2 * BSZ;
    constexpr int BN4 = NT / 32;                // B float4 loads per thread
    constexpr int NQ  = NT / 4;

    extern __shared__ char sm[];
    const uint32_t sbase = smem_u32(sm);

    const int tid  = threadIdx.x;
    const int lane = tid & 31;
    const int wid  = tid >> 5;
    const int wm   = wid / WARPS_N;
    const int wn   = wid % WARPS_N;

    const int bm = blockIdx.y * 128;
    const int bn = blockIdx.x * NT;
    const float* Ab = A + (long long)blockIdx.z * az + (size_t)bm * lda;
    const float* Bb = B + (long long)blockIdx.z * bz;
    float* Cb = C + (long long)blockIdx.z * cz;

    float acc[MT][4][4];
    #pragma unroll
    for (int mt = 0; mt < MT; mt++)
        #pragma unroll
        for (int nt = 0; nt < 4; nt++)
            #pragma unroll
            for (int r = 0; r < 4; r++) acc[mt][nt][r] = 0.f;

    const int NC = K >> 5;
    float4 ar[4];
    float4 br[BN4];

    // ---- prologue: load + store chunk 0
    #pragma unroll
    for (int i = 0; i < 4; i++) {
        int idx = tid + i * 256;
        ar[i] = *reinterpret_cast<const float4*>(
            &Ab[(size_t)(idx >> 3) * lda + ((idx & 7) << 2)]);
    }
    if (BNAT) {
        #pragma unroll
        for (int i = 0; i < BN4; i++) {
            int idx = tid + i * 256;
            br[i] = *reinterpret_cast<const float4*>(
                &Bb[(size_t)(bn + (idx >> 3)) * ldb + ((idx & 7) << 2)]);
        }
    } else {
        #pragma unroll
        for (int i = 0; i < BN4; i++) {
            int idx = tid + i * 256;
            br[i] = *reinterpret_cast<const float4*>(
                &Bb[(size_t)(idx / NQ) * ldb + bn + (idx % NQ) * 4]);
        }
    }
    {
        char* ah = sm;
        char* al = sm + ASZ;
        char* bh = sm + 2 * ASZ;
        char* bl = bh + BSZ;
        #pragma unroll
        for (int i = 0; i < 4; i++) {
            int idx = tid + i * 256;
            splitstore4(ar[i], ah, al,
                        ((idx >> 3) * 40 + ((idx & 7) << 2)) * 2, GELUA);
        }
        #pragma unroll
        for (int i = 0; i < BN4; i++) {
            int idx = tid + i * 256;
            int off = BNAT ? ((idx >> 3) * 40 + ((idx & 7) << 2)) * 2
                           : ((idx / NQ) * (NT + 8) + (idx % NQ) * 4) * 2;
            splitstore4(br[i], bh, bl, off, false);
        }
    }

    for (int c = 0; c < NC; c++) {
        __syncthreads();
        const int cur = c & 1;
        const bool more = (c + 1 < NC);
        const int k1 = (c + 1) << 5;

        if (more) {
            #pragma unroll
            for (int i = 0; i < 4; i++) {
                int idx = tid + i * 256;
                ar[i] = *reinterpret_cast<const float4*>(
                    &Ab[(size_t)(idx >> 3) * lda + k1 + ((idx & 7) << 2)]);
            }
            if (BNAT) {
                #pragma unroll
                for (int i = 0; i < BN4; i++) {
                    int idx = tid + i * 256;
                    br[i] = *reinterpret_cast<const float4*>(
                        &Bb[(size_t)(bn + (idx >> 3)) * ldb + k1 + ((idx & 7) << 2)]);
                }
            } else {
                #pragma unroll
                for (int i = 0; i < BN4; i++) {
                    int idx = tid + i * 256;
                    br[i] = *reinterpret_cast<const float4*>(
                        &Bb[(size_t)(k1 + idx / NQ) * ldb + bn + (idx % NQ) * 4]);
                }
            }
        }

        // ---- compute on buffer `cur`
        {
            const uint32_t abh = sbase + cur * STAGE;
            const uint32_t abl = abh + ASZ;
            const uint32_t bbh = abh + 2 * ASZ;
            const uint32_t bbl = bbh + BSZ;
            #pragma unroll
            for (int ks = 0; ks < 2; ks++) {
                uint32_t afh[MT][4], afl[MT][4], bfh[4][2], bfl[4][2];
                #pragma unroll
                for (int mt = 0; mt < MT; mt++) {
                    uint32_t off = ((wm * WM + mt * 16 + (lane & 15)) * 40 +
                                    ks * 16 + ((lane >> 4) << 3)) << 1;
                    LDSM_X4(afh[mt], abh + off);
                    LDSM_X4(afl[mt], abl + off);
                }
                #pragma unroll
                for (int nt = 0; nt < 4; nt++) {
                    if (BNAT) {
                        uint32_t off = ((wn * 32 + nt * 8 + (lane & 7)) * 40 +
                                        ks * 16 + (((lane >> 3) & 1) << 3)) << 1;
                        LDSM_X2(bfh[nt], bbh + off);
                        LDSM_X2(bfl[nt], bbl + off);
                    } else {
                        uint32_t off = ((ks * 16 + (lane & 15)) * (NT + 8) +
                                        wn * 32 + nt * 8) << 1;
                        LDSM_X2T(bfh[nt], bbh + off);
                        LDSM_X2T(bfl[nt], bbl + off);
                    }
                }
                #pragma unroll
                for (int nt = 0; nt < 4; nt++)
                    #pragma unroll
                    for (int mt = 0; mt < MT; mt++) {
                        MMA16816(acc[mt][nt], afh[mt], bfh[nt]);
                        MMA16816(acc[mt][nt], afh[mt], bfl[nt]);
                        MMA16816(acc[mt][nt], afl[mt], bfh[nt]);
                    }
            }
        }

        // ---- store prefetched chunk into other buffer
        if (more) {
            const int nxt = (c + 1) & 1;
            char* ah = sm + nxt * STAGE;
            char* al = ah + ASZ;
            char* bh = ah + 2 * ASZ;
            char* bl = bh + BSZ;
            #pragma unroll
            for (int i = 0; i < 4; i++) {
                int idx = tid + i * 256;
                splitstore4(ar[i], ah, al,
                            ((idx >> 3) * 40 + ((idx & 7) << 2)) * 2, GELUA);
            }
            #pragma unroll
            for (int i = 0; i < BN4; i++) {
                int idx = tid + i * 256;
                int off = BNAT ? ((idx >> 3) * 40 + ((idx & 7) << 2)) * 2
                               : ((idx / NQ) * (NT + 8) + (idx % NQ) * 4) * 2;
                splitstore4(br[i], bh, bl, off, false);
            }
        }
    }

    // ---- epilogue: direct float2 stores
    const int gid = lane >> 2, tig = lane & 3;
    #pragma unroll
    for (int mt = 0; mt < MT; mt++) {
        #pragma unroll
        for (int nt = 0; nt < 4; nt++) {
            int r0  = bm + wm * WM + mt * 16 + gid;
            int col = bn + wn * 32 + nt * 8 + tig * 2;
            float2 v0 = make_float2(acc[mt][nt][0] * scale, acc[mt][nt][1] * scale);
            float2 v1 = make_float2(acc[mt][nt][2] * scale, acc[mt][nt][3] * scale);
            if (EPI >= 1) {
                float2 bb = *reinterpret_cast<const float2*>(&bias[col]);
                v0.x += bb.x; v0.y += bb.y; v1.x += bb.x; v1.y += bb.y;
            }
            if (EPI == 2) {
                v0.x = gelu_f(v0.x); v0.y = gelu_f(v0.y);
                v1.x = gelu_f(v1.x); v1.y = gelu_f(v1.y);
            }
            if (EPI == 3) {
                float2 ra = *reinterpret_cast<const float2*>(
                    &res[(size_t)r0 * ldc + col]);
                float2 rb = *reinterpret_cast<const float2*>(
                    &res[(size_t)(r0 + 8) * ldc + col]);
                v0.x += ra.x; v0.y += ra.y; v1.x += rb.x; v1.y += rb.y;
            }
            *reinterpret_cast<float2*>(&Cb[(size_t)r0 * ldc + col]) = v0;
            *reinterpret_cast<float2*>(&Cb[(size_t)(r0 + 8) * ldc + col]) = v1;
        }
    }
}

// ---------------------------------------------------------------------------
// Elementwise / reduction kernels
// ---------------------------------------------------------------------------
__device__ __forceinline__ float blk_sum256(float v, float* sh) {
    int t = threadIdx.x;
    sh[t] = v; __syncthreads();
    #pragma unroll
    for (int s = 128; s >= 1; s >>= 1) {
        if (t < s) sh[t] += sh[t + s];
        __syncthreads();
    }
    float r = sh[0]; __syncthreads();
    return r;
}
__device__ __forceinline__ float blk_max256(float v, float* sh) {
    int t = threadIdx.x;
    sh[t] = v; __syncthreads();
    #pragma unroll
    for (int s = 128; s >= 1; s >>= 1) {
        if (t < s) sh[t] = fmaxf(sh[t], sh[t + s]);
        __syncthreads();
    }
    float r = sh[0]; __syncthreads();
    return r;
}

__global__ __launch_bounds__(256) void embed_kernel(
    const float* __restrict__ expr, const float* __restrict__ xt,
    const float* __restrict__ yt, const int* __restrict__ xi,
    const int* __restrict__ yi, float* __restrict__ out)
{
    int row = blockIdx.x;
    size_t xo = (size_t)xi[row] * SPOT;
    size_t yo = (size_t)yi[row] * SPOT;
    size_t ro = (size_t)row * SPOT;
    for (int j = threadIdx.x; j < SPOT; j += 256)
        out[ro + j] = expr[ro + j] + xt[xo + j] + yt[yo + j];
}

template<int CNT>
__global__ __launch_bounds__(256) void ln_kernel(
    const float* __restrict__ x, const float* __restrict__ g,
    const float* __restrict__ b, float* __restrict__ out)
{
    __shared__ float sh[256];
    const int N = CNT * 256;
    int row = blockIdx.x, tid = threadIdx.x;
    const float* xr = x + (size_t)row * N;
    float vals[CNT];
    float s = 0.f;
    #pragma unroll
    for (int i = 0; i < CNT; i++) { vals[i] = xr[i * 256 + tid]; s += vals[i]; }
    s = blk_sum256(s, sh);
    float mean = s / N;
    float ss = 0.f;
    #pragma unroll
    for (int i = 0; i < CNT; i++) { float d = vals[i] - mean; ss += d * d; }
    ss = blk_sum256(ss, sh);
    float rstd = rsqrtf(ss / N + 1e-5f);
    float* orow = out + (size_t)row * N;
    #pragma unroll
    for (int i = 0; i < CNT; i++) {
        int j = i * 256 + tid;
        orow[j] = (vals[i] - mean) * rstd * g[j] + b[j];
    }
}

__global__ __launch_bounds__(256) void softmax_rows(float* __restrict__ x)
{
    __shared__ float sh[256];
    size_t row = blockIdx.x;
    int tid = threadIdx.x;
    float* r = x + row * NB;
    float v[8];
    float mx = -1e30f;
    #pragma unroll
    for (int i = 0; i < 8; i++) { v[i] = r[i * 256 + tid]; mx = fmaxf(mx, v[i]); }
    mx = blk_max256(mx, sh);
    float s = 0.f;
    #pragma unroll
    for (int i = 0; i < 8; i++) { v[i] = __expf(v[i] - mx); s += v[i]; }
    s = blk_sum256(s, sh);
    float inv = 1.f / s;
    #pragma unroll
    for (int i = 0; i < 8; i++) r[i * 256 + tid] = v[i] * inv;
}

__global__ __launch_bounds__(256) void pack_kernel(
    const float* __restrict__ ie, const float* __restrict__ se,
    float* __restrict__ cat)
{
    int row = blockIdx.x;
    for (int j = threadIdx.x; j < 2 * PROJ; j += 256) {
        float v = (j < PROJ) ? ie[(size_t)row * PROJ + j]
                             : se[(size_t)row * PROJ + j - PROJ];
        cat[(size_t)row * 2 * PROJ + j] = v;
    }
}

__global__ __launch_bounds__(256) void rowloss_kernel(
    const float* __restrict__ logits, const float* __restrict__ tgt,
    float* __restrict__ rowp)
{
    __shared__ float sh[256];
    int row = blockIdx.x, tid = threadIdx.x;
    const float* lr = logits + (size_t)row * NB;
    const float* tr = tgt    + (size_t)row * NB;
    float lv[8], tv[8];
    float mx = -1e30f;
    #pragma unroll
    for (int i = 0; i < 8; i++) {
        lv[i] = lr[i * 256 + tid];
        tv[i] = tr[i * 256 + tid];
        mx = fmaxf(mx, lv[i]);
    }
    mx = blk_max256(mx, sh);
    float se = 0.f, dot = 0.f;
    #pragma unroll
    for (int i = 0; i < 8; i++) { se += __expf(lv[i] - mx); dot += tv[i] * lv[i]; }
    se  = blk_sum256(se, sh);
    dot = blk_sum256(dot, sh);
    if (tid == 0) rowp[row] = 0.5f * (mx + logf(se) - dot);
}

__global__ __launch_bounds__(256) void colloss_kernel(
    const float* __restrict__ logits, const float* __restrict__ tgt,
    float* __restrict__ colp)
{
    __shared__ float smx[256], sse[256], sts[256], stdot[256];
    int tid = threadIdx.x;
    int c = blockIdx.x * 64 + (tid & 63);
    int ry = tid >> 6;
    float mx = -1e30f, se = 0.f, ts = 0.f, td = 0.f;
    for (int r = ry; r < NB; r += 4) {
        float l = logits[(size_t)r * NB + c];
        float t = tgt   [(size_t)r * NB + c];
        if (l > mx) { se = se * __expf(mx - l) + 1.f; mx = l; }
        else        { se += __expf(l - mx); }
        ts += t;
        td += t * l;
    }
    smx[tid] = mx; sse[tid] = se; sts[tid] = ts; stdot[tid] = td;
    __syncthreads();
    if (ry == 0) {
        #pragma unroll
        for (int k = 1; k < 4; k++) {
            int o = tid + k * 64;
            float m2 = smx[o], s2 = sse[o];
            float m = fmaxf(mx, m2);
            se = se * __expf(mx - m) + s2 * __expf(m2 - m);
            mx = m;
            ts += sts[o];
            td += stdot[o];
        }
        colp[c] = 0.5f * (ts * (mx + logf(se)) - td);
    }
}

__global__ __launch_bounds__(256) void final_reduce(
    const float* __restrict__ a, const float* __restrict__ b,
    float* __restrict__ out)
{
    __shared__ float sh[256];
    int tid = threadIdx.x;
    float s = 0.f;
    for (int i = tid; i < NB; i += 256) s += a[i] + b[i];
    s = blk_sum256(s, sh);
    if (tid == 0) out[0] = s * (1.0f / NB);
}

// ---------------------------------------------------------------------------
// Host launch
// ---------------------------------------------------------------------------
namespace {
constexpr int smem_bytes(int NT, bool BNAT) {
    int BSZ = BNAT ? NT * 80 : 32 * (NT + 8) * 2;
    return 2 * (2 * 128 * 80 + 2 * BSZ);
}
constexpr int SM128T = smem_bytes(128, true);    // 81920
constexpr int SM128  = smem_bytes(128, false);   // 75776
constexpr int SM64   = smem_bytes(64,  false);   // 59392
}

extern "C" void kernel_launch(void* const* d_in, const int* in_sizes, int n_in,
                              void* d_out, int out_size)
{
    (void)in_sizes; (void)n_in; (void)out_size;
    const float* image_features = (const float*)d_in[0];
    const float* expression     = (const float*)d_in[1];
    const float* x_table        = (const float*)d_in[2];
    const float* y_table        = (const float*)d_in[3];
    const float* ln1_g          = (const float*)d_in[4];
    const float* ln1_b          = (const float*)d_in[5];
    const float* w_qkv          = (const float*)d_in[6];
    const float* w_o            = (const float*)d_in[7];
    const float* b_o            = (const float*)d_in[8];
    const float* ln2_g          = (const float*)d_in[9];
    const float* ln2_b          = (const float*)d_in[10];
    const float* w1             = (const float*)d_in[11];
    const float* b1             = (const float*)d_in[12];
    const float* w2             = (const float*)d_in[13];
    const float* b2             = (const float*)d_in[14];
    const float* img_proj_w     = (const float*)d_in[15];
    const float* img_proj_b     = (const float*)d_in[16];
    const float* img_fc_w       = (const float*)d_in[17];
    const float* img_fc_b       = (const float*)d_in[18];
    const float* img_ln_g       = (const float*)d_in[19];
    const float* img_ln_b       = (const float*)d_in[20];
    const float* spot_proj_w    = (const float*)d_in[21];
    const float* spot_proj_b    = (const float*)d_in[22];
    const float* spot_fc_w      = (const float*)d_in[23];
    const float* spot_fc_b      = (const float*)d_in[24];
    const float* spot_ln_g      = (const float*)d_in[25];
    const float* spot_ln_b      = (const float*)d_in[26];
    const int*   x_idx          = (const int*)d_in[27];
    const int*   y_idx          = (const int*)d_in[28];
    float* out = (float*)d_out;

    float *spot, *hbuf, *qkvb, *attno, *mlpb, *Sb;
    float *pimg, *eimg, *pspot, *espot, *cat, *logits, *tgt, *rowp, *colp;
    cudaGetSymbolAddress((void**)&spot,  g_spot);
    cudaGetSymbolAddress((void**)&hbuf,  g_hbuf);
    cudaGetSymbolAddress((void**)&qkvb,  g_qkv);
    cudaGetSymbolAddress((void**)&attno, g_attno);
    cudaGetSymbolAddress((void**)&mlpb,  g_mlp);
    cudaGetSymbolAddress((void**)&Sb,    g_S);
    cudaGetSymbolAddress((void**)&pimg,  g_pimg);
    cudaGetSymbolAddress((void**)&eimg,  g_eimg);
    cudaGetSymbolAddress((void**)&pspot, g_pspot);
    cudaGetSymbolAddress((void**)&espot, g_espot);
    cudaGetSymbolAddress((void**)&cat,   g_cat);
    cudaGetSymbolAddress((void**)&logits,g_logits);
    cudaGetSymbolAddress((void**)&tgt,   g_tgt);
    cudaGetSymbolAddress((void**)&rowp,  g_rowp);
    cudaGetSymbolAddress((void**)&colp,  g_colp);

    auto gNone   = gemm_mma<128, false, false, 0>;
    auto gNoneTB = gemm_mma<128, true,  false, 0>;
    auto gBias   = gemm_mma<128, false, false, 1>;
    auto gBGelu  = gemm_mma<128, false, false, 2>;
    auto gBRes   = gemm_mma<128, false, false, 3>;
    auto gFC     = gemm_mma<128, false, true,  3>;
    auto gPV     = gemm_mma<64,  false, false, 0>;
    cudaFuncSetAttribute(gNone,   cudaFuncAttributeMaxDynamicSharedMemorySize, SM128);
    cudaFuncSetAttribute(gNoneTB, cudaFuncAttributeMaxDynamicSharedMemorySize, SM128T);
    cudaFuncSetAttribute(gBias,   cudaFuncAttributeMaxDynamicSharedMemorySize, SM128);
    cudaFuncSetAttribute(gBGelu,  cudaFuncAttributeMaxDynamicSharedMemorySize, SM128);
    cudaFuncSetAttribute(gBRes,   cudaFuncAttributeMaxDynamicSharedMemorySize, SM128);
    cudaFuncSetAttribute(gFC,     cudaFuncAttributeMaxDynamicSharedMemorySize, SM128);
    cudaFuncSetAttribute(gPV,     cudaFuncAttributeMaxDynamicSharedMemorySize, SM64);

    const long long SZ = (long long)NB * NB;

    embed_kernel<<<NB, 256>>>(expression, x_table, y_table, x_idx, y_idx, spot);

    for (int l = 0; l < NL; l++) {
        const float* wqkv_l = w_qkv + (size_t)l * SPOT * QKVW;
        const float* wo_l   = w_o   + (size_t)l * INNER * SPOT;
        const float* bo_l   = b_o   + (size_t)l * SPOT;
        const float* w1_l   = w1    + (size_t)l * SPOT * MLPD;
        const float* b1_l   = b1    + (size_t)l * MLPD;
        const float* w2_l   = w2    + (size_t)l * MLPD * SPOT;
        const float* b2_l   = b2    + (size_t)l * SPOT;

        ln_kernel<4><<<NB, 256>>>(spot, ln1_g + l * SPOT, ln1_b + l * SPOT, hbuf);
        gNone<<<dim3(QKVW / 128, NB / 128, 1), 256, SM128>>>(
            hbuf, SPOT, 0, wqkv_l, QKVW, 0, nullptr, nullptr,
            qkvb, QKVW, 0, SPOT, 1.f);
        // S[h] = 0.125 * Q_h @ K_h^T
        gNoneTB<<<dim3(NB / 128, NB / 128, NH), 256, SM128T>>>(
            qkvb, QKVW, 64, qkvb + INNER, QKVW, 64, nullptr, nullptr,
            Sb, NB, SZ, DH, 0.125f);
        softmax_rows<<<NH * NB, 256>>>(Sb);
        // O_h = P_h @ V_h
        gPV<<<dim3(1, NB / 128, NH), 256, SM64>>>(
            Sb, NB, SZ, qkvb + 2 * INNER, QKVW, 64, nullptr, nullptr,
            attno, INNER, 64, NB, 1.f);
        gBRes<<<dim3(SPOT / 128, NB / 128, 1), 256, SM128>>>(
            attno, INNER, 0, wo_l, SPOT, 0, bo_l, spot,
            spot, SPOT, 0, INNER, 1.f);
        ln_kernel<4><<<NB, 256>>>(spot, ln2_g + l * SPOT, ln2_b + l * SPOT, hbuf);
        gBGelu<<<dim3(MLPD / 128, NB / 128, 1), 256, SM128>>>(
            hbuf, SPOT, 0, w1_l, MLPD, 0, b1_l, nullptr,
            mlpb, MLPD, 0, SPOT, 1.f);
        gBRes<<<dim3(SPOT / 128, NB / 128, 1), 256, SM128>>>(
            mlpb, MLPD, 0, w2_l, SPOT, 0, b2_l, spot,
            spot, SPOT, 0, MLPD, 1.f);
    }

    gBias<<<dim3(PROJ / 128, NB / 128, 1), 256, SM128>>>(
        image_features, IMG, 0, img_proj_w, PROJ, 0, img_proj_b, nullptr,
        pimg, PROJ, 0, IMG, 1.f);
    gFC<<<dim3(PROJ / 128, NB / 128, 1), 256, SM128>>>(
        pimg, PROJ, 0, img_fc_w, PROJ, 0, img_fc_b, pimg,
        eimg, PROJ, 0, PROJ, 1.f);
    ln_kernel<1><<<NB, 256>>>(eimg, img_ln_g, img_ln_b, eimg);

    gBias<<<dim3(PROJ / 128, NB / 128, 1), 256, SM128>>>(
        spot, SPOT, 0, spot_proj_w, PROJ, 0, spot_proj_b, nullptr,
        pspot, PROJ, 0, SPOT, 1.f);
    gFC<<<dim3(PROJ / 128, NB / 128, 1), 256, SM128>>>(
        pspot, PROJ, 0, spot_fc_w, PROJ, 0, spot_fc_b, pspot,
        espot, PROJ, 0, PROJ, 1.f);
    ln_kernel<1><<<NB, 256>>>(espot, spot_ln_g, spot_ln_b, espot);

    pack_kernel<<<NB, 256>>>(eimg, espot, cat);
    gNoneTB<<<dim3(NB / 128, NB / 128, 1), 256, SM128T>>>(
        espot, PROJ, 0, eimg, PROJ, 0, nullptr, nullptr,
        logits, NB, 0, PROJ, 1.f);
    gNoneTB<<<dim3(NB / 128, NB / 128, 1), 256, SM128T>>>(
        cat, 2 * PROJ, 0, cat, 2 * PROJ, 0, nullptr, nullptr,
        tgt, NB, 0, 2 * PROJ, 0.5f);
    softmax_rows<<<NB, 256>>>(tgt);
    rowloss_kernel<<<NB, 256>>>(logits, tgt, rowp);
    colloss_kernel<<<NB / 64, 256>>>(logits, tgt, colp);
    final_reduce<<<1, 256>>>(rowp, colp, out);
}